// round 9
// baseline (speedup 1.0000x reference)
#include <cuda_runtime.h>
#include <cstdint>
#include <cmath>

// Problem constants
#define EMB    1024
#define DIN    2048      // 2*EMB
#define HDIM   2048      // H
#define G4     8192      // 4*H
#define BB     1024      // batch
#define NSTEP  5
#define PATHL  11

// ---------------------------------------------------------------------------
// Scratch (device globals: allocation-free, graph-capture safe)
// ---------------------------------------------------------------------------
__device__ float g_X [NSTEP * BB * DIN];   // gathered LSTM inputs
__device__ float g_XW[NSTEP * BB * G4];    // X @ W_lstm + b (all steps)
__device__ float g_Z [BB * G4];
__device__ float g_h [BB * HDIM];
__device__ float g_c [BB * HDIM];
__device__ float g_A1[BB * DIN];
__device__ float g_A2[BB * DIN];

// ---------------------------------------------------------------------------
// Helpers
// ---------------------------------------------------------------------------
__device__ __forceinline__ uint32_t smem_u32(const void* p) {
    return (uint32_t)__cvta_generic_to_shared(p);
}

#define CP_ASYNC16(dst_u32, src_ptr)                                          \
    asm volatile("cp.async.cg.shared.global [%0], [%1], 16;\n"                \
                 :: "r"(dst_u32), "l"(src_ptr) : "memory")
#define CP_COMMIT()  asm volatile("cp.async.commit_group;\n" ::: "memory")
#define CP_WAIT(n)   asm volatile("cp.async.wait_group %0;\n" :: "n"(n) : "memory")

#define MMA_TF32(d, a, b)                                                     \
    asm volatile("mma.sync.aligned.m16n8k8.row.col.f32.tf32.tf32.f32 "        \
                 "{%0,%1,%2,%3}, {%4,%5,%6,%7}, {%8,%9}, {%0,%1,%2,%3};\n"    \
                 : "+f"((d)[0]), "+f"((d)[1]), "+f"((d)[2]), "+f"((d)[3])     \
                 : "r"((a)[0]), "r"((a)[1]), "r"((a)[2]), "r"((a)[3]),        \
                   "r"((b)[0]), "r"((b)[1]))

// ---------------------------------------------------------------------------
// 1) Gather: X[t*BB+b] = [emb[path[b,1+2t]], emb[path[b,2+2t]]]
// ---------------------------------------------------------------------------
__global__ void gather_kernel(const int* __restrict__ path,
                              const float* __restrict__ emb)
{
    int tb = blockIdx.x;            // t*1024 + b
    int t  = tb >> 10;
    int b  = tb & 1023;
    int p1 = path[b * PATHL + 1 + 2 * t];
    int p2 = path[b * PATHL + 2 + 2 * t];
    const float4* s1 = (const float4*)(emb + (size_t)p1 * EMB);
    const float4* s2 = (const float4*)(emb + (size_t)p2 * EMB);
    float4* dst = (float4*)(g_X + (size_t)tb * DIN);
    for (int i = threadIdx.x; i < EMB / 4; i += blockDim.x) {
        dst[i]           = s1[i];
        dst[i + EMB / 4] = s2[i];
    }
}

// ---------------------------------------------------------------------------
// 2) TF32 GEMM: C[M,N] = A[M,K] @ B[K,N] (+ epilogue)
//    mode 0: +bias[n]   mode 1: +addmat[m,n]   mode 2: relu(+bias[n])
//    M%128==0, N%64==0, K%64==0.
//    CTA tile 128x64, 256 threads, 8 warps (4M x 2N), warp tile 32x32.
//    ~80 regs/thread -> 3 CTAs/SM = 24 warps (latency-bound kernel: tput ∝ warps)
//    2-stage cp.async ring (smem limit with 3 CTAs/SM), R3-style intra-tile
//    fragment double buffering with the stage-wait folded into chunk 3.
// ---------------------------------------------------------------------------
#define BM 128
#define BN 64
#define BK 32
#define STAGES 2
#define AST 36            // A smem row stride (floats): conflict-free frag LDS
#define BST 72            // B smem row stride (floats): conflict-free frag LDS
#define A_STAGE (BM * AST)    // 4608 floats
#define B_STAGE (BK * BST)    // 2304 floats
#define SMEM_FLOATS (STAGES * (A_STAGE + B_STAGE))
#define SMEM_BYTES  (SMEM_FLOATS * 4)   // 55,296 B -> 3 CTAs = 166 KB

__global__ __launch_bounds__(256, 3)
void gemm_tf32(const float* __restrict__ A, const float* __restrict__ B,
               const float* __restrict__ bias, const float* __restrict__ addmat,
               float* __restrict__ C, int M, int N, int K, int mode)
{
    extern __shared__ float sm[];
    float* As = sm;
    float* Bs = sm + STAGES * A_STAGE;

    const int tid  = threadIdx.x;
    const int warp = tid >> 5;
    const int lane = tid & 31;
    const int wm   = (warp >> 1) * 32;   // 4 warps along M
    const int wn   = (warp & 1) * 32;    // 2 warps along N
    const int lg   = lane >> 2;
    const int lt   = lane & 3;
    const int bm   = blockIdx.y * BM;
    const int bn   = blockIdx.x * BN;

    // global->smem coords
    // A: 128 rows x 32 floats; thread t -> row t>>1, 16-float half (t&1), 4 chunks
    // B: 32 rows x 64 floats;  thread t -> row t>>3, 8-float seg (t&7), 2 chunks
    const int ar = tid >> 1;
    const int ac = (tid & 1) * 16;
    const int br = tid >> 3;
    const int bc = (tid & 7) * 8;

    const float* gA = A + (size_t)(bm + ar) * K + ac;
    const float* gB = B + (size_t)br * N + bn + bc;
    const uint32_t sAu = smem_u32(As);
    const uint32_t sBu = smem_u32(Bs);

    auto load_stage = [&](int slot, int k0) {
        uint32_t ab = sAu + (uint32_t)slot * (A_STAGE * 4);
        uint32_t bb = sBu + (uint32_t)slot * (B_STAGE * 4);
        const float* a0 = gA + k0;
        const float* b0 = gB + (size_t)k0 * N;
        #pragma unroll
        for (int c = 0; c < 4; c++)
            CP_ASYNC16(ab + (uint32_t)(ar * AST + ac + c * 4) * 4u, a0 + c * 4);
        #pragma unroll
        for (int c = 0; c < 2; c++)
            CP_ASYNC16(bb + (uint32_t)(br * BST + bc + c * 4) * 4u, b0 + c * 4);
    };

    uint32_t afr[2][2][4];
    uint32_t bfr[2][4][2];

    auto load_frags = [&](uint32_t (*af)[4], uint32_t (*bf)[2],
                          const float* sA, const float* sB, int kk) {
        #pragma unroll
        for (int i = 0; i < 2; i++) {
            const float* p = sA + (wm + i * 16 + lg) * AST + kk + lt;
            af[i][0] = __float_as_uint(p[0]);
            af[i][1] = __float_as_uint(p[8 * AST]);
            af[i][2] = __float_as_uint(p[4]);
            af[i][3] = __float_as_uint(p[8 * AST + 4]);
        }
        #pragma unroll
        for (int j = 0; j < 4; j++) {
            const float* p = sB + (kk + lt) * BST + wn + j * 8 + lg;
            bf[j][0] = __float_as_uint(p[0]);
            bf[j][1] = __float_as_uint(p[4 * BST]);
        }
    };

    float acc[2][4][4];
    #pragma unroll
    for (int i = 0; i < 2; i++)
        #pragma unroll
        for (int j = 0; j < 4; j++)
            #pragma unroll
            for (int q = 0; q < 4; q++) acc[i][j][q] = 0.0f;

    const int NT = K / BK;

    load_stage(0, 0); CP_COMMIT();
    CP_WAIT(0);
    __syncthreads();
    load_frags(afr[0], bfr[0], As, Bs, 0);

    for (int kt = 0; kt < NT; kt++) {
        // prefetch next tile into the other slot (consumed 1 iteration later)
        if (kt + 1 < NT) load_stage((kt + 1) & 1, (kt + 1) * BK);
        CP_COMMIT();
        const float* cA = As + (kt & 1) * A_STAGE;
        const float* cB = Bs + (kt & 1) * B_STAGE;
        #pragma unroll
        for (int kk = 0; kk < 4; kk++) {
            const int cur = kk & 1;
            const int nxt = cur ^ 1;
            if (kk < 3) {
                load_frags(afr[nxt], bfr[nxt], cA, cB, (kk + 1) * 8);
            } else if (kt + 1 < NT) {
                CP_WAIT(0);          // next tile resident
                __syncthreads();     // everyone done reading current slot
                const float* nA = As + ((kt + 1) & 1) * A_STAGE;
                const float* nB = Bs + ((kt + 1) & 1) * B_STAGE;
                load_frags(afr[nxt], bfr[nxt], nA, nB, 0);
            }
            #pragma unroll
            for (int i = 0; i < 2; i++)
                #pragma unroll
                for (int j = 0; j < 4; j++)
                    MMA_TF32(acc[i][j], afr[cur][i], bfr[cur][j]);
        }
    }

    // Epilogue: float2 stores (cols c0,c0+1 adjacent)
    #pragma unroll
    for (int i = 0; i < 2; i++) {
        #pragma unroll
        for (int j = 0; j < 4; j++) {
            const int r0 = bm + wm + i * 16 + lg;
            const int c0 = bn + wn + j * 8 + lt * 2;
            #pragma unroll
            for (int h = 0; h < 2; h++) {        // rows r0, r0+8
                const int r = r0 + h * 8;
                float vx = acc[i][j][h * 2 + 0];
                float vy = acc[i][j][h * 2 + 1];
                if (mode == 0) {
                    vx += bias[c0]; vy += bias[c0 + 1];
                } else if (mode == 1) {
                    const float2 av = *(const float2*)(addmat + (size_t)r * N + c0);
                    vx += av.x; vy += av.y;
                } else {
                    vx = fmaxf(vx + bias[c0],     0.0f);
                    vy = fmaxf(vy + bias[c0 + 1], 0.0f);
                }
                *(float2*)(C + (size_t)r * N + c0) = make_float2(vx, vy);
            }
        }
    }
}

// ---------------------------------------------------------------------------
// 3) LSTM cell
// ---------------------------------------------------------------------------
__global__ void lstm_cell(const float* __restrict__ Z, int first)
{
    int idx = blockIdx.x * blockDim.x + threadIdx.x;
    if (idx >= BB * HDIM) return;
    int b = idx >> 11;
    int j = idx & 2047;
    const float* zr = Z + (size_t)b * G4;
    float zi = zr[j];
    float zf = zr[j + HDIM];
    float zg = zr[j + 2 * HDIM];
    float zo = zr[j + 3 * HDIM];
    float ig = 1.0f / (1.0f + expf(-zi));
    float fg = 1.0f / (1.0f + expf(-zf));
    float gg = tanhf(zg);
    float og = 1.0f / (1.0f + expf(-zo));
    float cp = first ? 0.0f : g_c[idx];
    float cn = fg * cp + ig * gg;
    g_c[idx] = cn;
    g_h[idx] = og * tanhf(cn);
}

// ---------------------------------------------------------------------------
// 4) Head: logits = A2 @ W3 + b3 (N=2), softmax
// ---------------------------------------------------------------------------
__global__ void head_kernel(const float* __restrict__ W3,
                            const float* __restrict__ b3,
                            float* __restrict__ out)
{
    int b = blockIdx.x;
    const float* a = g_A2 + (size_t)b * DIN;
    float p0 = 0.0f, p1 = 0.0f;
    for (int k = threadIdx.x; k < DIN; k += blockDim.x) {
        float av = a[k];
        p0 += av * W3[k * 2 + 0];
        p1 += av * W3[k * 2 + 1];
    }
    #pragma unroll
    for (int o = 16; o > 0; o >>= 1) {
        p0 += __shfl_down_sync(0xFFFFFFFFu, p0, o);
        p1 += __shfl_down_sync(0xFFFFFFFFu, p1, o);
    }
    __shared__ float r0[8], r1[8];
    int warp = threadIdx.x >> 5, lane = threadIdx.x & 31;
    if (lane == 0) { r0[warp] = p0; r1[warp] = p1; }
    __syncthreads();
    if (threadIdx.x == 0) {
        float l0 = b3[0], l1 = b3[1];
        #pragma unroll
        for (int w = 0; w < 8; w++) { l0 += r0[w]; l1 += r1[w]; }
        float m = fmaxf(l0, l1);
        float e0 = expf(l0 - m), e1 = expf(l1 - m);
        float inv = 1.0f / (e0 + e1);
        out[b * 2 + 0] = e0 * inv;
        out[b * 2 + 1] = e1 * inv;
    }
}

// ---------------------------------------------------------------------------
// Launch
// ---------------------------------------------------------------------------
extern "C" void kernel_launch(void* const* d_in, const int* in_sizes, int n_in,
                              void* d_out, int out_size)
{
    (void)in_sizes; (void)n_in; (void)out_size;
    const int*   path   = (const int*)  d_in[0];
    const float* emb    = (const float*)d_in[1];
    const float* W_lstm = (const float*)d_in[2];
    const float* U_lstm = (const float*)d_in[3];
    const float* b_lstm = (const float*)d_in[4];
    const float* W1     = (const float*)d_in[5];
    const float* b1     = (const float*)d_in[6];
    const float* W2     = (const float*)d_in[7];
    const float* b2     = (const float*)d_in[8];
    const float* W3     = (const float*)d_in[9];
    const float* b3     = (const float*)d_in[10];
    float* out = (float*)d_out;

    float *X, *XW, *Z, *h, *A1, *A2;
    cudaGetSymbolAddress((void**)&X,  g_X);
    cudaGetSymbolAddress((void**)&XW, g_XW);
    cudaGetSymbolAddress((void**)&Z,  g_Z);
    cudaGetSymbolAddress((void**)&h,  g_h);
    cudaGetSymbolAddress((void**)&A1, g_A1);
    cudaGetSymbolAddress((void**)&A2, g_A2);

    cudaFuncSetAttribute(gemm_tf32, cudaFuncAttributeMaxDynamicSharedMemorySize,
                         SMEM_BYTES);

    // 1) gather inputs for all 5 steps
    gather_kernel<<<NSTEP * BB, 256>>>(path, emb);

    // 2) XW = X @ W_lstm + b_lstm  (M=5120, N=8192, K=2048)
    gemm_tf32<<<dim3(G4 / BN, (NSTEP * BB) / BM), 256, SMEM_BYTES>>>(
        X, W_lstm, b_lstm, nullptr, XW, NSTEP * BB, G4, DIN, 0);

    // 3) step 0 (h=0): cell directly on XW[0]
    lstm_cell<<<(BB * HDIM) / 256, 256>>>(XW, 1);

    // 4) steps 1..4: Z = h @ U_lstm + XW[t]; cell
    for (int t = 1; t < NSTEP; t++) {
        gemm_tf32<<<dim3(G4 / BN, BB / BM), 256, SMEM_BYTES>>>(
            h, U_lstm, nullptr, XW + (size_t)t * BB * G4, Z, BB, G4, HDIM, 1);
        lstm_cell<<<(BB * HDIM) / 256, 256>>>(Z, 0);
    }

    // 5) MLP
    gemm_tf32<<<dim3(DIN / BN, BB / BM), 256, SMEM_BYTES>>>(
        h,  W1, b1, nullptr, A1, BB, DIN, HDIM, 2);
    gemm_tf32<<<dim3(DIN / BN, BB / BM), 256, SMEM_BYTES>>>(
        A1, W2, b2, nullptr, A2, BB, DIN, DIN, 2);

    // 6) head + softmax
    head_kernel<<<BB, 256>>>(W3, b3, out);
}

// round 11
// speedup vs baseline: 1.1216x; 1.1216x over previous
#include <cuda_runtime.h>
#include <cstdint>
#include <cmath>

// Problem constants
#define EMB    1024
#define DIN    2048      // 2*EMB
#define HDIM   2048      // H
#define G4     8192      // 4*H
#define BB     1024      // batch
#define NSTEP  5
#define PATHL  11

// ---------------------------------------------------------------------------
// Scratch (device globals: allocation-free, graph-capture safe)
// ---------------------------------------------------------------------------
__device__ float g_X [NSTEP * BB * DIN];   // gathered LSTM inputs
__device__ float g_XW[NSTEP * BB * G4];    // X @ W_lstm + b (all steps)
__device__ float g_Z [BB * G4];
__device__ float g_h [BB * HDIM];
__device__ float g_c [BB * HDIM];
__device__ float g_A1[BB * DIN];
__device__ float g_A2[BB * DIN];

// ---------------------------------------------------------------------------
// Helpers
// ---------------------------------------------------------------------------
__device__ __forceinline__ uint32_t smem_u32(const void* p) {
    return (uint32_t)__cvta_generic_to_shared(p);
}

#define CP_ASYNC16(dst_u32, src_ptr)                                          \
    asm volatile("cp.async.cg.shared.global [%0], [%1], 16;\n"                \
                 :: "r"(dst_u32), "l"(src_ptr) : "memory")
#define CP_COMMIT()  asm volatile("cp.async.commit_group;\n" ::: "memory")
#define CP_WAIT(n)   asm volatile("cp.async.wait_group %0;\n" :: "n"(n) : "memory")

#define MMA_TF32(d, a, b)                                                     \
    asm volatile("mma.sync.aligned.m16n8k8.row.col.f32.tf32.tf32.f32 "        \
                 "{%0,%1,%2,%3}, {%4,%5,%6,%7}, {%8,%9}, {%0,%1,%2,%3};\n"    \
                 : "+f"((d)[0]), "+f"((d)[1]), "+f"((d)[2]), "+f"((d)[3])     \
                 : "r"((a)[0]), "r"((a)[1]), "r"((a)[2]), "r"((a)[3]),        \
                   "r"((b)[0]), "r"((b)[1]))

// ldmatrix x4 over b16: for tf32, one 8x4-tf32 tile == one 8x8-b16 matrix.
// Thread t receives 32-bit element (row t/4, col t%4) of its matrix -> exactly
// the mma.m16n8k8 tf32 A-fragment mapping (a0..a3 from the 4 matrices).
#define LDSM_X4(r0, r1, r2, r3, addr)                                         \
    asm volatile("ldmatrix.sync.aligned.m8n8.x4.shared.b16 {%0,%1,%2,%3}, [%4];" \
                 : "=r"(r0), "=r"(r1), "=r"(r2), "=r"(r3) : "r"(addr))

// ---------------------------------------------------------------------------
// 1) Gather: X[t*BB+b] = [emb[path[b,1+2t]], emb[path[b,2+2t]]]
// ---------------------------------------------------------------------------
__global__ void gather_kernel(const int* __restrict__ path,
                              const float* __restrict__ emb)
{
    int tb = blockIdx.x;            // t*1024 + b
    int t  = tb >> 10;
    int b  = tb & 1023;
    int p1 = path[b * PATHL + 1 + 2 * t];
    int p2 = path[b * PATHL + 2 + 2 * t];
    const float4* s1 = (const float4*)(emb + (size_t)p1 * EMB);
    const float4* s2 = (const float4*)(emb + (size_t)p2 * EMB);
    float4* dst = (float4*)(g_X + (size_t)tb * DIN);
    for (int i = threadIdx.x; i < EMB / 4; i += blockDim.x) {
        dst[i]           = s1[i];
        dst[i + EMB / 4] = s2[i];
    }
}

// ---------------------------------------------------------------------------
// 2) TF32 GEMM: C[M,N] = A[M,K] @ B[K,N] (+ epilogue)
//    mode 0: +bias[n]   mode 1: +addmat[m,n]   mode 2: relu(+bias[n])
//    M%128==0, N%128==0, K%64==0. 256 threads, 8 warps (2M x 4N), warp 64x32.
//    R3 pipeline (3-stage cp.async ring, frag double buffer, wait folded into
//    chunk 3) + ldmatrix.x4 for A fragments (4 LDSM replace 16 LDS.32/chunk).
// ---------------------------------------------------------------------------
#define BM 128
#define BN 128
#define BK 32
#define STAGES 3
#define AST 36            // A smem row stride (floats): 144B -> rows on distinct bank quads
#define BST 136           // B smem row stride (floats)
#define A_STAGE (BM * AST)    // 4608 floats
#define B_STAGE (BK * BST)    // 4352 floats
#define SMEM_FLOATS (STAGES * (A_STAGE + B_STAGE))
#define SMEM_BYTES  (SMEM_FLOATS * 4)   // 107,520 B

__global__ __launch_bounds__(256, 2)
void gemm_tf32(const float* __restrict__ A, const float* __restrict__ B,
               const float* __restrict__ bias, const float* __restrict__ addmat,
               float* __restrict__ C, int M, int N, int K, int mode)
{
    extern __shared__ float sm[];
    float* As = sm;
    float* Bs = sm + STAGES * A_STAGE;

    const int tid  = threadIdx.x;
    const int warp = tid >> 5;
    const int lane = tid & 31;
    const int wm   = (warp & 1) * 64;
    const int wn   = (warp >> 1) * 32;
    const int lg   = lane >> 2;
    const int lt   = lane & 3;
    const int bm   = blockIdx.y * BM;
    const int bn   = blockIdx.x * BN;

    // ldmatrix lane-address components: lanes 0-15 -> rows 0-15 (k 0-3),
    // lanes 16-31 -> rows 0-15 (k 4-7)
    const int lrow = lane & 15;
    const int lcol = (lane >> 4) << 2;

    // global->smem coords: A 128x32 (4 x float4/thread), B 32x128 (4 x float4)
    const int ar = tid >> 2;            // 0..63 (+64)
    const int ac = (tid & 3) * 4;       // 0,4,8,12 (+16)
    const int br = tid >> 3;            // 0..31
    const int bc = (tid & 7) * 4;       // 0..28 (+32,+64,+96)

    const float* gA = A + (size_t)(bm + ar) * K + ac;
    const float* gB = B + (size_t)br * N + bn + bc;
    const uint32_t sAu = smem_u32(As);
    const uint32_t sBu = smem_u32(Bs);

    auto load_stage = [&](int slot, int k0) {
        uint32_t ab = sAu + (uint32_t)slot * (A_STAGE * 4);
        uint32_t bb = sBu + (uint32_t)slot * (B_STAGE * 4);
        const float* a0 = gA + k0;
        const float* b0 = gB + (size_t)k0 * N;
        #pragma unroll
        for (int s = 0; s < 2; s++)
            #pragma unroll
            for (int c = 0; c < 2; c++)
                CP_ASYNC16(ab + (uint32_t)((ar + s * 64) * AST + ac + c * 16) * 4u,
                           a0 + (size_t)s * 64 * K + c * 16);
        #pragma unroll
        for (int c = 0; c < 4; c++)
            CP_ASYNC16(bb + (uint32_t)(br * BST + bc + c * 32) * 4u,
                       b0 + c * 32);
    };

    uint32_t afr[2][4][4];
    uint32_t bfr[2][4][2];

    auto load_frags = [&](uint32_t (*af)[4], uint32_t (*bf)[2],
                          const float* sA, const float* sB, int kk) {
        #pragma unroll
        for (int i = 0; i < 4; i++) {
            uint32_t ad = smem_u32(sA + (wm + i * 16 + lrow) * AST + kk + lcol);
            LDSM_X4(af[i][0], af[i][1], af[i][2], af[i][3], ad);
        }
        #pragma unroll
        for (int j = 0; j < 4; j++) {
            const float* p = sB + (kk + lt) * BST + wn + j * 8 + lg;
            bf[j][0] = __float_as_uint(p[0]);
            bf[j][1] = __float_as_uint(p[4 * BST]);
        }
    };

    float acc[4][4][4];
    #pragma unroll
    for (int i = 0; i < 4; i++)
        #pragma unroll
        for (int j = 0; j < 4; j++)
            #pragma unroll
            for (int q = 0; q < 4; q++) acc[i][j][q] = 0.0f;

    const int NT = K / BK;

    load_stage(0, 0);  CP_COMMIT();
    load_stage(1, BK); CP_COMMIT();
    CP_WAIT(1);
    __syncthreads();
    load_frags(afr[0], bfr[0], As, Bs, 0);

    for (int kt = 0; kt < NT; kt++) {
        if (kt + 2 < NT) load_stage((kt + 2) % STAGES, (kt + 2) * BK);
        CP_COMMIT();
        const float* cA = As + (kt % STAGES) * A_STAGE;
        const float* cB = Bs + (kt % STAGES) * B_STAGE;
        #pragma unroll
        for (int kk = 0; kk < 4; kk++) {
            const int cur = kk & 1;
            const int nxt = cur ^ 1;
            if (kk < 3) {
                load_frags(afr[nxt], bfr[nxt], cA, cB, (kk + 1) * 8);
            } else if (kt + 1 < NT) {
                CP_WAIT(1);          // stage kt+1 resident
                __syncthreads();     // everyone done reading slot kt
                const float* nA = As + ((kt + 1) % STAGES) * A_STAGE;
                const float* nB = Bs + ((kt + 1) % STAGES) * B_STAGE;
                load_frags(afr[nxt], bfr[nxt], nA, nB, 0);
            }
            #pragma unroll
            for (int i = 0; i < 4; i++)
                #pragma unroll
                for (int j = 0; j < 4; j++)
                    MMA_TF32(acc[i][j], afr[cur][i], bfr[cur][j]);
        }
    }

    // Epilogue: float2 stores (cols c0,c0+1 adjacent)
    #pragma unroll
    for (int i = 0; i < 4; i++) {
        #pragma unroll
        for (int j = 0; j < 4; j++) {
            const int r0 = bm + wm + i * 16 + lg;
            const int c0 = bn + wn + j * 8 + lt * 2;
            #pragma unroll
            for (int h = 0; h < 2; h++) {        // rows r0, r0+8
                const int r = r0 + h * 8;
                float vx = acc[i][j][h * 2 + 0];
                float vy = acc[i][j][h * 2 + 1];
                if (mode == 0) {
                    vx += bias[c0]; vy += bias[c0 + 1];
                } else if (mode == 1) {
                    const float2 av = *(const float2*)(addmat + (size_t)r * N + c0);
                    vx += av.x; vy += av.y;
                } else {
                    vx = fmaxf(vx + bias[c0],     0.0f);
                    vy = fmaxf(vy + bias[c0 + 1], 0.0f);
                }
                *(float2*)(C + (size_t)r * N + c0) = make_float2(vx, vy);
            }
        }
    }
}

// ---------------------------------------------------------------------------
// 3) LSTM cell
// ---------------------------------------------------------------------------
__global__ void lstm_cell(const float* __restrict__ Z, int first)
{
    int idx = blockIdx.x * blockDim.x + threadIdx.x;
    if (idx >= BB * HDIM) return;
    int b = idx >> 11;
    int j = idx & 2047;
    const float* zr = Z + (size_t)b * G4;
    float zi = zr[j];
    float zf = zr[j + HDIM];
    float zg = zr[j + 2 * HDIM];
    float zo = zr[j + 3 * HDIM];
    float ig = 1.0f / (1.0f + expf(-zi));
    float fg = 1.0f / (1.0f + expf(-zf));
    float gg = tanhf(zg);
    float og = 1.0f / (1.0f + expf(-zo));
    float cp = first ? 0.0f : g_c[idx];
    float cn = fg * cp + ig * gg;
    g_c[idx] = cn;
    g_h[idx] = og * tanhf(cn);
}

// ---------------------------------------------------------------------------
// 4) Head: logits = A2 @ W3 + b3 (N=2), softmax
// ---------------------------------------------------------------------------
__global__ void head_kernel(const float* __restrict__ W3,
                            const float* __restrict__ b3,
                            float* __restrict__ out)
{
    int b = blockIdx.x;
    const float* a = g_A2 + (size_t)b * DIN;
    float p0 = 0.0f, p1 = 0.0f;
    for (int k = threadIdx.x; k < DIN; k += blockDim.x) {
        float av = a[k];
        p0 += av * W3[k * 2 + 0];
        p1 += av * W3[k * 2 + 1];
    }
    #pragma unroll
    for (int o = 16; o > 0; o >>= 1) {
        p0 += __shfl_down_sync(0xFFFFFFFFu, p0, o);
        p1 += __shfl_down_sync(0xFFFFFFFFu, p1, o);
    }
    __shared__ float r0[8], r1[8];
    int warp = threadIdx.x >> 5, lane = threadIdx.x & 31;
    if (lane == 0) { r0[warp] = p0; r1[warp] = p1; }
    __syncthreads();
    if (threadIdx.x == 0) {
        float l0 = b3[0], l1 = b3[1];
        #pragma unroll
        for (int w = 0; w < 8; w++) { l0 += r0[w]; l1 += r1[w]; }
        float m = fmaxf(l0, l1);
        float e0 = expf(l0 - m), e1 = expf(l1 - m);
        float inv = 1.0f / (e0 + e1);
        out[b * 2 + 0] = e0 * inv;
        out[b * 2 + 1] = e1 * inv;
    }
}

// ---------------------------------------------------------------------------
// Launch
// ---------------------------------------------------------------------------
extern "C" void kernel_launch(void* const* d_in, const int* in_sizes, int n_in,
                              void* d_out, int out_size)
{
    (void)in_sizes; (void)n_in; (void)out_size;
    const int*   path   = (const int*)  d_in[0];
    const float* emb    = (const float*)d_in[1];
    const float* W_lstm = (const float*)d_in[2];
    const float* U_lstm = (const float*)d_in[3];
    const float* b_lstm = (const float*)d_in[4];
    const float* W1     = (const float*)d_in[5];
    const float* b1     = (const float*)d_in[6];
    const float* W2     = (const float*)d_in[7];
    const float* b2     = (const float*)d_in[8];
    const float* W3     = (const float*)d_in[9];
    const float* b3     = (const float*)d_in[10];
    float* out = (float*)d_out;

    float *X, *XW, *Z, *h, *A1, *A2;
    cudaGetSymbolAddress((void**)&X,  g_X);
    cudaGetSymbolAddress((void**)&XW, g_XW);
    cudaGetSymbolAddress((void**)&Z,  g_Z);
    cudaGetSymbolAddress((void**)&h,  g_h);
    cudaGetSymbolAddress((void**)&A1, g_A1);
    cudaGetSymbolAddress((void**)&A2, g_A2);

    cudaFuncSetAttribute(gemm_tf32, cudaFuncAttributeMaxDynamicSharedMemorySize,
                         SMEM_BYTES);

    // 1) gather inputs for all 5 steps
    gather_kernel<<<NSTEP * BB, 256>>>(path, emb);

    // 2) XW = X @ W_lstm + b_lstm  (M=5120, N=8192, K=2048)
    gemm_tf32<<<dim3(G4 / BN, (NSTEP * BB) / BM), 256, SMEM_BYTES>>>(
        X, W_lstm, b_lstm, nullptr, XW, NSTEP * BB, G4, DIN, 0);

    // 3) step 0 (h=0): cell directly on XW[0]
    lstm_cell<<<(BB * HDIM) / 256, 256>>>(XW, 1);

    // 4) steps 1..4: Z = h @ U_lstm + XW[t]; cell
    for (int t = 1; t < NSTEP; t++) {
        gemm_tf32<<<dim3(G4 / BN, BB / BM), 256, SMEM_BYTES>>>(
            h, U_lstm, nullptr, XW + (size_t)t * BB * G4, Z, BB, G4, HDIM, 1);
        lstm_cell<<<(BB * HDIM) / 256, 256>>>(Z, 0);
    }

    // 5) MLP
    gemm_tf32<<<dim3(DIN / BN, BB / BM), 256, SMEM_BYTES>>>(
        h,  W1, b1, nullptr, A1, BB, DIN, HDIM, 2);
    gemm_tf32<<<dim3(DIN / BN, BB / BM), 256, SMEM_BYTES>>>(
        A1, W2, b2, nullptr, A2, BB, DIN, DIN, 2);

    // 6) head + softmax
    head_kernel<<<BB, 256>>>(W3, b3, out);
}

// round 12
// speedup vs baseline: 2.0545x; 1.8318x over previous
#include <cuda_runtime.h>
#include <cuda_fp16.h>
#include <cstdint>
#include <cmath>

// Problem constants
#define EMB    1024
#define DIN    2048      // 2*EMB
#define HDIM   2048      // H
#define G4     8192      // 4*H
#define BB     1024      // batch
#define NSTEP  5
#define PATHL  11

// ---------------------------------------------------------------------------
// Scratch (device globals: allocation-free, graph-capture safe)
// ---------------------------------------------------------------------------
__device__ __half   g_Xh [NSTEP * BB * DIN];      // gathered inputs (fp16)
__device__ uint32_t g_Wp [(DIN  / 2) * G4];       // W_lstm packed k-pairs
__device__ uint32_t g_Up [(HDIM / 2) * G4];       // U_lstm packed
__device__ uint32_t g_W1p[(HDIM / 2) * DIN];      // W1 packed
__device__ uint32_t g_W2p[(DIN  / 2) * DIN];      // W2 packed
__device__ float    g_XW [NSTEP * BB * G4];       // X @ W_lstm + b (fp32)
__device__ float    g_Z  [BB * G4];
__device__ __half   g_hh [BB * HDIM];             // h (fp16, feeds GEMMs)
__device__ float    g_c  [BB * HDIM];
__device__ __half   g_A1h[BB * DIN];              // relu MLP1 out (fp16)
__device__ float    g_A2 [BB * DIN];              // relu MLP2 out (fp32)

// ---------------------------------------------------------------------------
// Helpers
// ---------------------------------------------------------------------------
__device__ __forceinline__ uint32_t smem_u32(const void* p) {
    return (uint32_t)__cvta_generic_to_shared(p);
}

#define CP_ASYNC16(dst_u32, src_ptr)                                          \
    asm volatile("cp.async.cg.shared.global [%0], [%1], 16;\n"                \
                 :: "r"(dst_u32), "l"(src_ptr) : "memory")
#define CP_COMMIT()  asm volatile("cp.async.commit_group;\n" ::: "memory")
#define CP_WAIT(n)   asm volatile("cp.async.wait_group %0;\n" :: "n"(n) : "memory")

// fp16 MMA, fp32 accumulate: 2x the FLOPs/issue of tf32 k8
#define MMA_F16(d, a, b)                                                      \
    asm volatile("mma.sync.aligned.m16n8k16.row.col.f32.f16.f16.f32 "         \
                 "{%0,%1,%2,%3}, {%4,%5,%6,%7}, {%8,%9}, {%0,%1,%2,%3};\n"    \
                 : "+f"((d)[0]), "+f"((d)[1]), "+f"((d)[2]), "+f"((d)[3])     \
                 : "r"((a)[0]), "r"((a)[1]), "r"((a)[2]), "r"((a)[3]),        \
                   "r"((b)[0]), "r"((b)[1]))

// ---------------------------------------------------------------------------
// 1) Gather (fp32 emb -> fp16 X): X[t*BB+b] = [emb[p1], emb[p2]]
// ---------------------------------------------------------------------------
__global__ void gather_kernel(const int* __restrict__ path,
                              const float* __restrict__ emb)
{
    int tb = blockIdx.x;            // t*1024 + b
    int t  = tb >> 10;
    int b  = tb & 1023;
    int p1 = path[b * PATHL + 1 + 2 * t];
    int p2 = path[b * PATHL + 2 + 2 * t];
    const float4* s1 = (const float4*)(emb + (size_t)p1 * EMB);
    const float4* s2 = (const float4*)(emb + (size_t)p2 * EMB);
    __half2* dst = (__half2*)(g_Xh + (size_t)tb * DIN);
    for (int i = threadIdx.x; i < EMB / 4; i += blockDim.x) {
        float4 v1 = s1[i];
        float4 v2 = s2[i];
        dst[i * 2 + 0]               = __floats2half2_rn(v1.x, v1.y);
        dst[i * 2 + 1]               = __floats2half2_rn(v1.z, v1.w);
        dst[EMB / 2 + i * 2 + 0]     = __floats2half2_rn(v2.x, v2.y);
        dst[EMB / 2 + i * 2 + 1]     = __floats2half2_rn(v2.z, v2.w);
    }
}

// ---------------------------------------------------------------------------
// 2) Pack weights: W[K][N] fp32 -> Wp[K/2][N] u32 (half2 of k, k+1)
// ---------------------------------------------------------------------------
__global__ void pack_w(const float* __restrict__ W, uint32_t* __restrict__ Wp,
                       int K, int N)
{
    int idx = blockIdx.x * blockDim.x + threadIdx.x;
    if (idx >= (K / 2) * N) return;
    int kp = idx / N;
    int n  = idx - kp * N;
    float f0 = W[(size_t)(2 * kp)     * N + n];
    float f1 = W[(size_t)(2 * kp + 1) * N + n];
    __half2 h = __floats2half2_rn(f0, f1);   // .x = k (low), .y = k+1 (high)
    Wp[idx] = *(const uint32_t*)&h;
}

// ---------------------------------------------------------------------------
// 3) FP16 GEMM: C[M,N] = A[M,K] @ B[K,N] (+ epilogue). A fp16 row-major,
//    B pre-packed [K/2][N] u32 (k-pair per reg = exact m16n8k16 B fragment).
//    mode 0: +bias, f32 out     mode 1: +addmat, f32 out
//    mode 2: relu(+bias), f16 out    mode 3: relu(+bias), f32 out
//    M%128==0, N%128==0, K%64==0. 256 threads, 8 warps (2M x 4N), warp 64x32.
//    R3 pipeline: 3-stage cp.async ring, BK=64 (4 k16-chunks), fragment
//    double buffer, stage-wait folded into chunk 3. Same smem byte geometry
//    and bank pattern as the proven tf32 kernel.
// ---------------------------------------------------------------------------
#define BM 128
#define BN 128
#define BK 64
#define STAGES 3
#define ASTU 36           // A row stride in u32 units (= 72 halves = 144 B)
#define BSTU 136          // B row stride in u32 units (544 B)
#define A_STAGE_U (BM * ASTU)     // 4608 u32
#define B_STAGE_U ((BK / 2) * BSTU)  // 32 kpair rows * 136 = 4352 u32
#define SMEM_U32S (STAGES * (A_STAGE_U + B_STAGE_U))
#define SMEM_BYTES (SMEM_U32S * 4)   // 107,520 B

__global__ __launch_bounds__(256, 2)
void gemm_f16(const __half* __restrict__ A, const uint32_t* __restrict__ Bp,
              const float* __restrict__ bias, const float* __restrict__ addmat,
              void* __restrict__ Cv, int M, int N, int K, int mode)
{
    extern __shared__ uint32_t sm[];
    uint32_t* As = sm;                       // A tiles, u32 view (2 halves/u32)
    uint32_t* Bs = sm + STAGES * A_STAGE_U;  // B tiles (packed k-pairs)

    const int tid  = threadIdx.x;
    const int warp = tid >> 5;
    const int lane = tid & 31;
    const int wm   = (warp & 1) * 64;
    const int wn   = (warp >> 1) * 32;
    const int lg   = lane >> 2;
    const int lt   = lane & 3;
    const int bm   = blockIdx.y * BM;
    const int bn   = blockIdx.x * BN;

    // global->smem coords
    // A: 128 rows x 64 halves (128B data/row); 2 threads/row, 4x16B each
    // B: 32 kpair-rows x 128 u32 (512B/row); 8 threads/row, 4x16B each
    const int ar = tid >> 1;            // 0..127
    const int acb = (tid & 1) * 4;      // chunk base 0 or 4 (16B chunks)
    const int br = tid >> 3;            // 0..31
    const int bseg = (tid & 7) * 16;    // u32 segment base

    const __half* gA = A + (size_t)(bm + ar) * K;
    const uint32_t sAu = smem_u32(As);
    const uint32_t sBu = smem_u32(Bs);

    auto load_stage = [&](int slot, int k0) {
        uint32_t ab = sAu + (uint32_t)slot * (A_STAGE_U * 4);
        uint32_t bb = sBu + (uint32_t)slot * (B_STAGE_U * 4);
        const __half* a0 = gA + k0;
        const uint32_t* b0 = Bp + (size_t)(k0 / 2 + br) * N + bn + bseg;
        #pragma unroll
        for (int c = 0; c < 4; c++) {
            int ch = acb + c;           // 16B chunk index within row (0..7)
            CP_ASYNC16(ab + (uint32_t)(ar * (ASTU * 4) + ch * 16),
                       a0 + ch * 8);
            CP_ASYNC16(bb + (uint32_t)(br * (BSTU * 4) + (bseg + c * 4) * 4),
                       b0 + c * 4);
        }
    };

    uint32_t afr[2][4][4];
    uint32_t bfr[2][4][2];

    // chunk c covers k = 16c..16c+15 (u32 cols 8c..8c+7; kpair rows 8c..8c+7)
    auto load_frags = [&](uint32_t (*af)[4], uint32_t (*bf)[2],
                          const uint32_t* sA, const uint32_t* sB, int c) {
        #pragma unroll
        for (int i = 0; i < 4; i++) {
            const uint32_t* p = sA + (wm + i * 16 + lg) * ASTU + c * 8 + lt;
            af[i][0] = p[0];
            af[i][1] = p[8 * ASTU];
            af[i][2] = p[4];
            af[i][3] = p[8 * ASTU + 4];
        }
        #pragma unroll
        for (int j = 0; j < 4; j++) {
            const uint32_t* p = sB + (c * 8 + lt) * BSTU + wn + j * 8 + lg;
            bf[j][0] = p[0];
            bf[j][1] = p[4 * BSTU];
        }
    };

    float acc[4][4][4];
    #pragma unroll
    for (int i = 0; i < 4; i++)
        #pragma unroll
        for (int j = 0; j < 4; j++)
            #pragma unroll
            for (int q = 0; q < 4; q++) acc[i][j][q] = 0.0f;

    const int NT = K / BK;   // 32 for K=2048

    load_stage(0, 0);  CP_COMMIT();
    load_stage(1, BK); CP_COMMIT();
    CP_WAIT(1);
    __syncthreads();
    load_frags(afr[0], bfr[0], As, Bs, 0);

    for (int kt = 0; kt < NT; kt++) {
        if (kt + 2 < NT) load_stage((kt + 2) % STAGES, (kt + 2) * BK);
        CP_COMMIT();
        const uint32_t* cA = As + (kt % STAGES) * A_STAGE_U;
        const uint32_t* cB = Bs + (kt % STAGES) * B_STAGE_U;
        #pragma unroll
        for (int kk = 0; kk < 4; kk++) {
            const int cur = kk & 1;
            const int nxt = cur ^ 1;
            if (kk < 3) {
                load_frags(afr[nxt], bfr[nxt], cA, cB, kk + 1);
            } else if (kt + 1 < NT) {
                CP_WAIT(1);          // stage kt+1 resident
                __syncthreads();     // everyone done reading slot kt
                const uint32_t* nA = As + ((kt + 1) % STAGES) * A_STAGE_U;
                const uint32_t* nB = Bs + ((kt + 1) % STAGES) * B_STAGE_U;
                load_frags(afr[nxt], bfr[nxt], nA, nB, 0);
            }
            #pragma unroll
            for (int i = 0; i < 4; i++)
                #pragma unroll
                for (int j = 0; j < 4; j++)
                    MMA_F16(acc[i][j], afr[cur][i], bfr[cur][j]);
        }
    }

    // Epilogue
    #pragma unroll
    for (int i = 0; i < 4; i++) {
        #pragma unroll
        for (int j = 0; j < 4; j++) {
            const int r0 = bm + wm + i * 16 + lg;
            const int c0 = bn + wn + j * 8 + lt * 2;
            #pragma unroll
            for (int h = 0; h < 2; h++) {        // rows r0, r0+8
                const int r = r0 + h * 8;
                float vx = acc[i][j][h * 2 + 0];
                float vy = acc[i][j][h * 2 + 1];
                if (mode == 0) {
                    vx += bias[c0]; vy += bias[c0 + 1];
                    *(float2*)((float*)Cv + (size_t)r * N + c0) = make_float2(vx, vy);
                } else if (mode == 1) {
                    const float2 av = *(const float2*)(addmat + (size_t)r * N + c0);
                    vx += av.x; vy += av.y;
                    *(float2*)((float*)Cv + (size_t)r * N + c0) = make_float2(vx, vy);
                } else if (mode == 2) {
                    vx = fmaxf(vx + bias[c0],     0.0f);
                    vy = fmaxf(vy + bias[c0 + 1], 0.0f);
                    *(__half2*)((__half*)Cv + (size_t)r * N + c0) =
                        __floats2half2_rn(vx, vy);
                } else {
                    vx = fmaxf(vx + bias[c0],     0.0f);
                    vy = fmaxf(vy + bias[c0 + 1], 0.0f);
                    *(float2*)((float*)Cv + (size_t)r * N + c0) = make_float2(vx, vy);
                }
            }
        }
    }
}

// ---------------------------------------------------------------------------
// 4) LSTM cell: gates from Z fp32; writes h as fp16 (GEMM input) + c fp32
// ---------------------------------------------------------------------------
__global__ void lstm_cell(const float* __restrict__ Z, int first)
{
    int idx = blockIdx.x * blockDim.x + threadIdx.x;
    if (idx >= BB * HDIM) return;
    int b = idx >> 11;
    int j = idx & 2047;
    const float* zr = Z + (size_t)b * G4;
    float zi = zr[j];
    float zf = zr[j + HDIM];
    float zg = zr[j + 2 * HDIM];
    float zo = zr[j + 3 * HDIM];
    float ig = 1.0f / (1.0f + expf(-zi));
    float fg = 1.0f / (1.0f + expf(-zf));
    float gg = tanhf(zg);
    float og = 1.0f / (1.0f + expf(-zo));
    float cp = first ? 0.0f : g_c[idx];
    float cn = fg * cp + ig * gg;
    g_c[idx]  = cn;
    g_hh[idx] = __float2half(og * tanhf(cn));
}

// ---------------------------------------------------------------------------
// 5) Head: logits = A2 @ W3 + b3 (N=2), softmax
// ---------------------------------------------------------------------------
__global__ void head_kernel(const float* __restrict__ W3,
                            const float* __restrict__ b3,
                            float* __restrict__ out)
{
    int b = blockIdx.x;
    const float* a = g_A2 + (size_t)b * DIN;
    float p0 = 0.0f, p1 = 0.0f;
    for (int k = threadIdx.x; k < DIN; k += blockDim.x) {
        float av = a[k];
        p0 += av * W3[k * 2 + 0];
        p1 += av * W3[k * 2 + 1];
    }
    #pragma unroll
    for (int o = 16; o > 0; o >>= 1) {
        p0 += __shfl_down_sync(0xFFFFFFFFu, p0, o);
        p1 += __shfl_down_sync(0xFFFFFFFFu, p1, o);
    }
    __shared__ float r0[8], r1[8];
    int warp = threadIdx.x >> 5, lane = threadIdx.x & 31;
    if (lane == 0) { r0[warp] = p0; r1[warp] = p1; }
    __syncthreads();
    if (threadIdx.x == 0) {
        float l0 = b3[0], l1 = b3[1];
        #pragma unroll
        for (int w = 0; w < 8; w++) { l0 += r0[w]; l1 += r1[w]; }
        float m = fmaxf(l0, l1);
        float e0 = expf(l0 - m), e1 = expf(l1 - m);
        float inv = 1.0f / (e0 + e1);
        out[b * 2 + 0] = e0 * inv;
        out[b * 2 + 1] = e1 * inv;
    }
}

// ---------------------------------------------------------------------------
// Launch
// ---------------------------------------------------------------------------
extern "C" void kernel_launch(void* const* d_in, const int* in_sizes, int n_in,
                              void* d_out, int out_size)
{
    (void)in_sizes; (void)n_in; (void)out_size;
    const int*   path   = (const int*)  d_in[0];
    const float* emb    = (const float*)d_in[1];
    const float* W_lstm = (const float*)d_in[2];
    const float* U_lstm = (const float*)d_in[3];
    const float* b_lstm = (const float*)d_in[4];
    const float* W1     = (const float*)d_in[5];
    const float* b1     = (const float*)d_in[6];
    const float* W2     = (const float*)d_in[7];
    const float* b2     = (const float*)d_in[8];
    const float* W3     = (const float*)d_in[9];
    const float* b3     = (const float*)d_in[10];
    float* out = (float*)d_out;

    __half *Xh, *hh, *A1h;
    uint32_t *Wp, *Up, *W1p, *W2p;
    float *XW, *Z, *A2;
    cudaGetSymbolAddress((void**)&Xh,  g_Xh);
    cudaGetSymbolAddress((void**)&Wp,  g_Wp);
    cudaGetSymbolAddress((void**)&Up,  g_Up);
    cudaGetSymbolAddress((void**)&W1p, g_W1p);
    cudaGetSymbolAddress((void**)&W2p, g_W2p);
    cudaGetSymbolAddress((void**)&XW,  g_XW);
    cudaGetSymbolAddress((void**)&Z,   g_Z);
    cudaGetSymbolAddress((void**)&hh,  g_hh);
    cudaGetSymbolAddress((void**)&A1h, g_A1h);
    cudaGetSymbolAddress((void**)&A2,  g_A2);

    cudaFuncSetAttribute(gemm_f16, cudaFuncAttributeMaxDynamicSharedMemorySize,
                         SMEM_BYTES);

    // 1) gather (fp16) + pack all weights to k-pair u32 layout
    gather_kernel<<<NSTEP * BB, 256>>>(path, emb);
    pack_w<<<((DIN / 2) * G4 + 255) / 256, 256>>>(W_lstm, Wp,  DIN,  G4);
    pack_w<<<((HDIM / 2) * G4 + 255) / 256, 256>>>(U_lstm, Up,  HDIM, G4);
    pack_w<<<((HDIM / 2) * DIN + 255) / 256, 256>>>(W1,    W1p, HDIM, DIN);
    pack_w<<<((DIN / 2) * DIN + 255) / 256, 256>>>(W2,     W2p, DIN,  DIN);

    // 2) XW = X @ W_lstm + b_lstm  (M=5120, N=8192, K=2048)
    gemm_f16<<<dim3(G4 / BN, (NSTEP * BB) / BM), 256, SMEM_BYTES>>>(
        Xh, Wp, b_lstm, nullptr, XW, NSTEP * BB, G4, DIN, 0);

    // 3) step 0 (h=0): cell directly on XW[0]
    lstm_cell<<<(BB * HDIM) / 256, 256>>>(XW, 1);

    // 4) steps 1..4: Z = h @ U_lstm + XW[t]; cell
    for (int t = 1; t < NSTEP; t++) {
        gemm_f16<<<dim3(G4 / BN, BB / BM), 256, SMEM_BYTES>>>(
            hh, Up, nullptr, XW + (size_t)t * BB * G4, Z, BB, G4, HDIM, 1);
        lstm_cell<<<(BB * HDIM) / 256, 256>>>(Z, 0);
    }

    // 5) MLP: A1h = relu(h@W1+b1) fp16; A2 = relu(A1@W2+b2) fp32
    gemm_f16<<<dim3(DIN / BN, BB / BM), 256, SMEM_BYTES>>>(
        hh,  W1p, b1, nullptr, A1h, BB, DIN, HDIM, 2);
    gemm_f16<<<dim3(DIN / BN, BB / BM), 256, SMEM_BYTES>>>(
        A1h, W2p, b2, nullptr, A2,  BB, DIN, DIN, 3);

    // 6) head + softmax
    head_kernel<<<BB, 256>>>(W3, b3, out);
}